// round 1
// baseline (speedup 1.0000x reference)
#include <cuda_runtime.h>
#include <math.h>

#define NN   50000
#define EE   500000
#define GG   64
#define DIN  128
#define ED   32
#define H1   256
#define H2   128
#define HD   64
#define OUTD 8

// ---------------- scratch (device globals; no allocation allowed) ----------
__device__ float g_xl[(size_t)NN * H1];
__device__ float g_xr[(size_t)NN * H1];
__device__ float g_h1[(size_t)NN * H1];
__device__ float g_h2[(size_t)NN * H2];
__device__ float g_ew[(size_t)EE * H1];      // edge_attr @ We (layer-sized rows)
__device__ float g_escore[EE];
__device__ float g_eself[NN];
__device__ float g_loopattr[(size_t)NN * ED];
__device__ int   g_deg[NN];
__device__ int   g_ptr[NN + 1];
__device__ int   g_cur[NN];
__device__ int   g_eid[EE];
__device__ float g_pool[GG * H2];
__device__ float g_cnt[GG];

// ---------------- init ----------------
__global__ void k_zero_all() {
    int stride = gridDim.x * blockDim.x;
    int tid0 = blockIdx.x * blockDim.x + threadIdx.x;
    for (int t = tid0; t < NN * ED; t += stride) g_loopattr[t] = 0.f;
    for (int t = tid0; t < NN; t += stride) { g_deg[t] = 0; g_cur[t] = 0; }
    for (int t = tid0; t < GG * H2; t += stride) g_pool[t] = 0.f;
    for (int t = tid0; t < GG; t += stride) g_cnt[t] = 0.f;
}

// histogram of in-degree + accumulate edge_attr per dst (for self-loop mean)
__global__ void k_edge_hist(const int* __restrict__ edst,
                            const float* __restrict__ eattr) {
    int gw = (blockIdx.x * blockDim.x + threadIdx.x) >> 5;
    int lane = threadIdx.x & 31;
    if (gw >= EE) return;
    int d = edst[gw];
    if (lane == 0) atomicAdd(&g_deg[d], 1);
    atomicAdd(&g_loopattr[(size_t)d * ED + lane], eattr[(size_t)gw * ED + lane]);
}

__global__ void k_loop_div() {
    int i = blockIdx.x * blockDim.x + threadIdx.x;
    if (i >= NN * ED) return;
    int node = i / ED;
    g_loopattr[i] /= fmaxf((float)g_deg[node], 1.f);
}

// exclusive scan of degrees -> CSR row pointers (single block; tiny cost)
__global__ void k_scan() {
    __shared__ int sh[1024];
    __shared__ int carry;
    if (threadIdx.x == 0) carry = 0;
    __syncthreads();
    for (int base = 0; base < NN; base += 1024) {
        int i = base + threadIdx.x;
        int v = (i < NN) ? g_deg[i] : 0;
        sh[threadIdx.x] = v;
        __syncthreads();
        for (int off = 1; off < 1024; off <<= 1) {
            int t = (threadIdx.x >= off) ? sh[threadIdx.x - off] : 0;
            __syncthreads();
            sh[threadIdx.x] += t;
            __syncthreads();
        }
        if (i < NN) g_ptr[i] = carry + sh[threadIdx.x] - v;
        __syncthreads();
        if (threadIdx.x == 0) carry += sh[1023];
        __syncthreads();
    }
    if (threadIdx.x == 0) g_ptr[NN] = EE;
}

__global__ void k_scatter(const int* __restrict__ edst) {
    int e = blockIdx.x * blockDim.x + threadIdx.x;
    if (e >= EE) return;
    int d = edst[e];
    int pos = atomicAdd(&g_cur[d], 1);
    g_eid[g_ptr[d] + pos] = e;
}

// ---------------- SGEMM: C[M,Nc] = A[M,K] @ B[K,Nc] (+bias) ----------------
// 64x64 tile, BK=16, 4x4 per thread, 256 threads. Nc % 64 == 0, K % 16 == 0.
__global__ void k_sgemm(const float* __restrict__ A, const float* __restrict__ B,
                        const float* __restrict__ bias, float* __restrict__ C,
                        int M, int Nc, int K) {
    __shared__ float As[64][16];
    __shared__ float Bs[16][64];
    int tid = threadIdx.x;
    int tx = tid & 15, ty = tid >> 4;
    int rowBase = blockIdx.x * 64, colBase = blockIdx.y * 64;
    float acc[4][4];
#pragma unroll
    for (int i = 0; i < 4; i++)
#pragma unroll
        for (int j = 0; j < 4; j++) acc[i][j] = 0.f;

    for (int k0 = 0; k0 < K; k0 += 16) {
#pragma unroll
        for (int l = 0; l < 4; l++) {
            int idx = tid + l * 256;
            int r = idx >> 4, c = idx & 15;
            As[r][c] = (rowBase + r < M) ? A[(size_t)(rowBase + r) * K + k0 + c] : 0.f;
            int br = idx >> 6, bc = idx & 63;
            Bs[br][bc] = B[(size_t)(k0 + br) * Nc + colBase + bc];
        }
        __syncthreads();
#pragma unroll
        for (int k = 0; k < 16; k++) {
            float a[4];
#pragma unroll
            for (int i = 0; i < 4; i++) a[i] = As[ty * 4 + i][k];
            float4 b4 = *(const float4*)(&Bs[k][tx * 4]);
            float b[4] = {b4.x, b4.y, b4.z, b4.w};
#pragma unroll
            for (int i = 0; i < 4; i++)
#pragma unroll
                for (int j = 0; j < 4; j++) acc[i][j] += a[i] * b[j];
        }
        __syncthreads();
    }
#pragma unroll
    for (int i = 0; i < 4; i++) {
        int r = rowBase + ty * 4 + i;
        if (r < M) {
#pragma unroll
            for (int j = 0; j < 4; j++) {
                int c = colBase + tx * 4 + j;
                C[(size_t)r * Nc + c] = acc[i][j] + (bias ? bias[c] : 0.f);
            }
        }
    }
}

// ---------------- self-loop score per node ----------------
template <int C>
__global__ void k_eself(const float* __restrict__ We, const float* __restrict__ att,
                        const float* __restrict__ xl, const float* __restrict__ xr) {
    int gw = (blockIdx.x * blockDim.x + threadIdx.x) >> 5;
    int lane = threadIdx.x & 31;
    if (gw >= NN) return;
    float la = g_loopattr[(size_t)gw * ED + lane];
    float acc = 0.f;
#pragma unroll
    for (int jj = 0; jj < C / 32; jj++) {
        int j = jj * 32 + lane;
        float v = xl[(size_t)gw * C + j] + xr[(size_t)gw * C + j];
#pragma unroll
        for (int k = 0; k < ED; k++)
            v += __shfl_sync(0xffffffffu, la, k) * We[k * C + j];
        v = v > 0.f ? v : 0.2f * v;
        acc += att[j] * v;
    }
#pragma unroll
    for (int off = 16; off; off >>= 1) acc += __shfl_xor_sync(0xffffffffu, acc, off);
    if (lane == 0) g_eself[gw] = acc;
}

// ---------------- per-edge attention score ----------------
template <int C>
__global__ void k_score(const int* __restrict__ esrc, const int* __restrict__ edst,
                        const float* __restrict__ att,
                        const float* __restrict__ xl, const float* __restrict__ xr) {
    int gw = (blockIdx.x * blockDim.x + threadIdx.x) >> 5;
    int lane = threadIdx.x & 31;
    if (gw >= EE) return;
    int s = esrc[gw], d = edst[gw];
    float acc = 0.f;
#pragma unroll
    for (int jj = 0; jj < C / 32; jj++) {
        int j = jj * 32 + lane;
        float v = xl[(size_t)s * C + j] + xr[(size_t)d * C + j] + g_ew[(size_t)gw * C + j];
        v = v > 0.f ? v : 0.2f * v;
        acc += att[j] * v;
    }
#pragma unroll
    for (int off = 16; off; off >>= 1) acc += __shfl_xor_sync(0xffffffffu, acc, off);
    if (lane == 0) g_escore[gw] = acc;
}

// ---------------- softmax + aggregation per dst node (warp/node, no atomics)
template <int C>
__global__ void k_aggregate(const int* __restrict__ esrc,
                            const float* __restrict__ xl,
                            const float* __restrict__ bias,
                            float* __restrict__ outp) {
    int gw = (blockIdx.x * blockDim.x + threadIdx.x) >> 5;
    int lane = threadIdx.x & 31;
    if (gw >= NN) return;
    int beg = g_ptr[gw], end = g_ptr[gw + 1];

    float m = g_eself[gw];
    for (int t = beg + lane; t < end; t += 32) m = fmaxf(m, g_escore[g_eid[t]]);
#pragma unroll
    for (int off = 16; off; off >>= 1) m = fmaxf(m, __shfl_xor_sync(0xffffffffu, m, off));

    float acc[C / 32];
#pragma unroll
    for (int jj = 0; jj < C / 32; jj++) acc[jj] = 0.f;
    float denom = 0.f;

    for (int t = beg; t < end; t++) {
        int eid = g_eid[t];
        float w = expf(g_escore[eid] - m);
        int s = esrc[eid];
        denom += w;
#pragma unroll
        for (int jj = 0; jj < C / 32; jj++)
            acc[jj] += w * xl[(size_t)s * C + jj * 32 + lane];
    }
    float ws = expf(g_eself[gw] - m);
    denom += ws;
#pragma unroll
    for (int jj = 0; jj < C / 32; jj++)
        acc[jj] += ws * xl[(size_t)gw * C + jj * 32 + lane];

    float inv = 1.f / denom;
#pragma unroll
    for (int jj = 0; jj < C / 32; jj++) {
        int j = jj * 32 + lane;
        outp[(size_t)gw * C + j] = fmaxf(acc[jj] * inv + bias[j], 0.f);  // fused ReLU
    }
}

// ---------------- global mean pool ----------------
__global__ void k_pool(const int* __restrict__ batch) {
    int stride = gridDim.x * blockDim.x;
    int tid0 = blockIdx.x * blockDim.x + threadIdx.x;
    for (int t = tid0; t < NN * H2; t += stride) {
        int node = t / H2;
        atomicAdd(&g_pool[batch[node] * H2 + (t - node * H2)], g_h2[t]);
    }
    for (int t = tid0; t < NN; t += stride)
        atomicAdd(&g_cnt[batch[t]], 1.f);
}

// ---------------- MLP head (single block) ----------------
__global__ void k_head(const float* __restrict__ Wd1, const float* __restrict__ bd1,
                       const float* __restrict__ gma, const float* __restrict__ bta,
                       const float* __restrict__ mean, const float* __restrict__ var,
                       const float* __restrict__ Wd2, const float* __restrict__ bd2,
                       float* __restrict__ out) {
    __shared__ float sp[GG * H2];   // 32 KB
    __shared__ float sh[GG * HD];   // 16 KB
    int tid = threadIdx.x;
    for (int idx = tid; idx < GG * H2; idx += blockDim.x) {
        int g = idx / H2;
        sp[idx] = g_pool[idx] / fmaxf(g_cnt[g], 1.f);
    }
    __syncthreads();
    for (int idx = tid; idx < GG * HD; idx += blockDim.x) {
        int g = idx / HD, h = idx - g * HD;
        float a = bd1[h];
        for (int k = 0; k < H2; k++) a += sp[g * H2 + k] * Wd1[k * HD + h];
        a = (a - mean[h]) / sqrtf(var[h] + 1e-5f) * gma[h] + bta[h];
        a = a > 0.f ? a : 0.1f * a;
        sh[idx] = a;
    }
    __syncthreads();
    for (int idx = tid; idx < GG * OUTD; idx += blockDim.x) {
        int g = idx / OUTD, o = idx - g * OUTD;
        float a = bd2[o];
        for (int k = 0; k < HD; k++) a += sh[g * HD + k] * Wd2[k * OUTD + o];
        out[idx] = a;
    }
}

// ---------------- launcher ----------------
extern "C" void kernel_launch(void* const* d_in, const int* in_sizes, int n_in,
                              void* d_out, int out_size) {
    const float* node_attr = (const float*)d_in[0];
    const float* edge_attr = (const float*)d_in[1];
    const int*   esrc      = (const int*)d_in[2];
    const int*   edst      = (const int*)d_in[3];
    const int*   batch     = (const int*)d_in[4];
    const float *Wl1 = (const float*)d_in[5],  *bl1 = (const float*)d_in[6];
    const float *Wr1 = (const float*)d_in[7],  *br1 = (const float*)d_in[8];
    const float *We1 = (const float*)d_in[9],  *att1 = (const float*)d_in[10], *b1 = (const float*)d_in[11];
    const float *Wl2 = (const float*)d_in[12], *bl2 = (const float*)d_in[13];
    const float *Wr2 = (const float*)d_in[14], *br2 = (const float*)d_in[15];
    const float *We2 = (const float*)d_in[16], *att2 = (const float*)d_in[17], *b2 = (const float*)d_in[18];
    const float *Wd1 = (const float*)d_in[19], *bd1 = (const float*)d_in[20];
    const float *gma = (const float*)d_in[21], *bta = (const float*)d_in[22];
    const float *mean = (const float*)d_in[23], *var = (const float*)d_in[24];
    const float *Wd2 = (const float*)d_in[25], *bd2 = (const float*)d_in[26];
    float* out = (float*)d_out;

    float *p_xl, *p_xr, *p_h1, *p_h2, *p_ew;
    cudaGetSymbolAddress((void**)&p_xl, g_xl);
    cudaGetSymbolAddress((void**)&p_xr, g_xr);
    cudaGetSymbolAddress((void**)&p_h1, g_h1);
    cudaGetSymbolAddress((void**)&p_h2, g_h2);
    cudaGetSymbolAddress((void**)&p_ew, g_ew);

    // graph structure (shared by both layers)
    k_zero_all<<<512, 256>>>();
    k_edge_hist<<<(EE * 32 + 255) / 256, 256>>>(edst, edge_attr);
    k_loop_div<<<(NN * ED + 255) / 256, 256>>>();
    k_scan<<<1, 1024>>>();
    k_scatter<<<(EE + 255) / 256, 256>>>(edst);

    int nodeWB = (NN * 32 + 255) / 256;   // warp-per-node blocks
    int edgeWB = (EE * 32 + 255) / 256;   // warp-per-edge blocks

    // ---------------- layer 1 (DIN=128 -> H1=256) ----------------
    {
        dim3 gx((NN + 63) / 64, H1 / 64);
        k_sgemm<<<gx, 256>>>(node_attr, Wl1, bl1, p_xl, NN, H1, DIN);
        k_sgemm<<<gx, 256>>>(node_attr, Wr1, br1, p_xr, NN, H1, DIN);
        dim3 ge((EE + 63) / 64, H1 / 64);
        k_sgemm<<<ge, 256>>>(edge_attr, We1, nullptr, p_ew, EE, H1, ED);
        k_eself<H1><<<nodeWB, 256>>>(We1, att1, p_xl, p_xr);
        k_score<H1><<<edgeWB, 256>>>(esrc, edst, att1, p_xl, p_xr);
        k_aggregate<H1><<<nodeWB, 256>>>(esrc, p_xl, b1, p_h1);
    }
    // ---------------- layer 2 (H1=256 -> H2=128) ----------------
    {
        dim3 gx((NN + 63) / 64, H2 / 64);
        k_sgemm<<<gx, 256>>>(p_h1, Wl2, bl2, p_xl, NN, H2, H1);
        k_sgemm<<<gx, 256>>>(p_h1, Wr2, br2, p_xr, NN, H2, H1);
        dim3 ge((EE + 63) / 64, H2 / 64);
        k_sgemm<<<ge, 256>>>(edge_attr, We2, nullptr, p_ew, EE, H2, ED);
        k_eself<H2><<<nodeWB, 256>>>(We2, att2, p_xl, p_xr);
        k_score<H2><<<edgeWB, 256>>>(esrc, edst, att2, p_xl, p_xr);
        k_aggregate<H2><<<nodeWB, 256>>>(esrc, p_xl, b2, p_h2);
    }
    // ---------------- pool + head ----------------
    k_pool<<<2048, 256>>>(batch);
    k_head<<<1, 512>>>(Wd1, bd1, gma, bta, mean, var, Wd2, bd2, out);
}

// round 2
// speedup vs baseline: 1.0932x; 1.0932x over previous
#include <cuda_runtime.h>
#include <math.h>

#define NN   50000
#define EE   500000
#define GG   64
#define DIN  128
#define ED   32
#define H1   256
#define H2   128
#define HD   64
#define OUTD 8
#define NCHUNK 49   // ceil(NN/1024)

// ---------------- scratch (device globals; no allocation allowed) ----------
__device__ float g_xl[(size_t)NN * H1];
__device__ float g_xr[(size_t)NN * H1];
__device__ float g_h1[(size_t)NN * H1];
__device__ float g_h2[(size_t)NN * H2];
__device__ float g_escore[EE];
__device__ float g_eself[NN];
__device__ float g_loopattr[(size_t)NN * ED];
__device__ int   g_deg[NN];
__device__ int   g_ptr[NN + 1];
__device__ int   g_cur[NN];
__device__ int   g_eid[EE];
__device__ int   g_bsum[64];
__device__ float g_pool[GG * H2];

// ---------------- f32x2 packed helpers ----------------
__device__ __forceinline__ unsigned long long ffma2(unsigned long long a,
                                                    unsigned long long b,
                                                    unsigned long long c) {
    unsigned long long d;
    asm("fma.rn.f32x2 %0, %1, %2, %3;" : "=l"(d) : "l"(a), "l"(b), "l"(c));
    return d;
}
__device__ __forceinline__ unsigned long long dup2(float x) {
    unsigned int u = __float_as_uint(x);
    return ((unsigned long long)u << 32) | (unsigned long long)u;
}
__device__ __forceinline__ float2 unpk(unsigned long long v) {
    float2 r;
    r.x = __uint_as_float((unsigned int)(v & 0xffffffffull));
    r.y = __uint_as_float((unsigned int)(v >> 32));
    return r;
}

// ---------------- degree histogram (int atomics) ----------------
__global__ void k_hist(const int* __restrict__ edst) {
    int e = blockIdx.x * blockDim.x + threadIdx.x;
    if (e < EE) atomicAdd(&g_deg[edst[e]], 1);
}

// ---------------- multi-block exclusive scan of g_deg -> g_ptr ------------
__global__ void k_scan_partial() {
    __shared__ int sh[32];
    int tid = threadIdx.x;
    int i = blockIdx.x * 1024 + tid;
    int v = (i < NN) ? g_deg[i] : 0;
#pragma unroll
    for (int o = 16; o; o >>= 1) v += __shfl_xor_sync(0xffffffffu, v, o);
    if ((tid & 31) == 0) sh[tid >> 5] = v;
    __syncthreads();
    if (tid < 32) {
        int t = sh[tid];
#pragma unroll
        for (int o = 16; o; o >>= 1) t += __shfl_xor_sync(0xffffffffu, t, o);
        if (tid == 0) g_bsum[blockIdx.x] = t;
    }
}

__global__ void k_scan_bsum() {
    __shared__ int sh[64];
    int tid = threadIdx.x;
    int v = (tid < NCHUNK) ? g_bsum[tid] : 0;
    sh[tid] = v;
    __syncthreads();
    for (int off = 1; off < 64; off <<= 1) {
        int t = (tid >= off) ? sh[tid - off] : 0;
        __syncthreads();
        sh[tid] += t;
        __syncthreads();
    }
    if (tid < NCHUNK) g_bsum[tid] = sh[tid] - v;   // exclusive
    if (tid == 0) g_ptr[NN] = EE;
}

__global__ void k_scan_final() {
    __shared__ int sh[32];
    int tid = threadIdx.x, lane = tid & 31, wid = tid >> 5;
    int i = blockIdx.x * 1024 + tid;
    int v = (i < NN) ? g_deg[i] : 0;
    int incl = v;
#pragma unroll
    for (int o = 1; o < 32; o <<= 1) {
        int t = __shfl_up_sync(0xffffffffu, incl, o);
        if (lane >= o) incl += t;
    }
    if (lane == 31) sh[wid] = incl;
    __syncthreads();
    if (wid == 0) {
        int t = sh[lane];
#pragma unroll
        for (int o = 1; o < 32; o <<= 1) {
            int u = __shfl_up_sync(0xffffffffu, t, o);
            if (lane >= o) t += u;
        }
        sh[lane] = t;
    }
    __syncthreads();
    int base = g_bsum[blockIdx.x] + (wid ? sh[wid - 1] : 0);
    if (i < NN) g_ptr[i] = base + incl - v;
}

__global__ void k_scatter(const int* __restrict__ edst) {
    int e = blockIdx.x * blockDim.x + threadIdx.x;
    if (e >= EE) return;
    int d = edst[e];
    int pos = atomicAdd(&g_cur[d], 1);
    g_eid[g_ptr[d] + pos] = e;
}

// ---------------- per-node mean of incoming edge_attr (atomic-free) -------
__global__ void k_loopmean(const float* __restrict__ eattr) {
    int gw = (blockIdx.x * blockDim.x + threadIdx.x) >> 5;
    int lane = threadIdx.x & 31;
    if (gw >= NN) return;
    int beg = g_ptr[gw], end = g_ptr[gw + 1];
    float acc = 0.f;
    for (int t = beg; t < end; t++)
        acc += eattr[(size_t)g_eid[t] * ED + lane];
    g_loopattr[(size_t)gw * ED + lane] = acc / fmaxf((float)(end - beg), 1.f);
}

// ---------------- SGEMM (128x128 tile, 8x8/thread, packed f32x2) ----------
__global__ void __launch_bounds__(256, 2)
k_sgemm2(const float* __restrict__ A, const float* __restrict__ B,
         const float* __restrict__ bias, float* __restrict__ C,
         int M, int Nc, int K) {
    __shared__ __align__(16) unsigned long long As2[16][128];  // dup-packed [k][row]
    __shared__ __align__(16) float Bs[16][128];                // [k][col]
    int tid = threadIdx.x;
    int tx = tid & 15, ty = tid >> 4;
    int rowBase = blockIdx.x * 128, colBase = blockIdx.y * 128;
    unsigned long long acc2[8][4];
#pragma unroll
    for (int i = 0; i < 8; i++)
#pragma unroll
        for (int j = 0; j < 4; j++) acc2[i][j] = 0ull;

    for (int k0 = 0; k0 < K; k0 += 16) {
#pragma unroll
        for (int s = 0; s < 2; s++) {
            int r = (tid >> 2) + s * 64;
            int c = (tid & 3) * 4;
            float4 v = make_float4(0.f, 0.f, 0.f, 0.f);
            if (rowBase + r < M)
                v = *(const float4*)&A[(size_t)(rowBase + r) * K + k0 + c];
            As2[c + 0][r] = dup2(v.x);
            As2[c + 1][r] = dup2(v.y);
            As2[c + 2][r] = dup2(v.z);
            As2[c + 3][r] = dup2(v.w);
        }
#pragma unroll
        for (int s = 0; s < 2; s++) {
            int r = s * 8 + (tid >> 5);
            int c = (tid & 31) * 4;
            *(float4*)&Bs[r][c] = *(const float4*)&B[(size_t)(k0 + r) * Nc + colBase + c];
        }
        __syncthreads();
#pragma unroll
        for (int k = 0; k < 16; k++) {
            unsigned long long a2[8];
#pragma unroll
            for (int i = 0; i < 8; i++) a2[i] = As2[k][ty * 8 + i];
            ulonglong2 b01 = *(const ulonglong2*)&Bs[k][tx * 8];
            ulonglong2 b23 = *(const ulonglong2*)&Bs[k][tx * 8 + 4];
            unsigned long long b2[4] = {b01.x, b01.y, b23.x, b23.y};
#pragma unroll
            for (int i = 0; i < 8; i++)
#pragma unroll
                for (int j = 0; j < 4; j++)
                    acc2[i][j] = ffma2(a2[i], b2[j], acc2[i][j]);
        }
        __syncthreads();
    }
#pragma unroll
    for (int i = 0; i < 8; i++) {
        int r = rowBase + ty * 8 + i;
        if (r < M) {
#pragma unroll
            for (int j = 0; j < 4; j++) {
                float2 v = unpk(acc2[i][j]);
                int c = colBase + tx * 8 + 2 * j;
                C[(size_t)r * Nc + c]     = v.x + bias[c];
                C[(size_t)r * Nc + c + 1] = v.y + bias[c + 1];
            }
        }
    }
}

// ---------------- fused edge-score GEMM -----------------------------------
// For a 64-edge x 64-col tile: ew = eattr@We (K=32), then
// partial_e = sum_cols att[c] * leakyrelu(ew + xl[src][c] + xr[dst][c]),
// atomically accumulated into g_escore[e] across column blocks.
template <int C>
__global__ void k_score_gemm(const float* __restrict__ eattr,
                             const float* __restrict__ We,
                             const int* __restrict__ esrc,
                             const int* __restrict__ edst,
                             const float* __restrict__ att,
                             const float* __restrict__ xl,
                             const float* __restrict__ xr) {
    __shared__ __align__(16) unsigned long long As2[32][64];  // dup-packed [k][edge]
    __shared__ __align__(16) float Bs[32][64];                // We [k][col]
    __shared__ int ssrc[64], sdst[64];
    __shared__ __align__(16) float satt[64];
    int tid = threadIdx.x;
    int tx = tid & 15, ty = tid >> 4;
    int r0 = blockIdx.x * 64, c0 = blockIdx.y * 64;

#pragma unroll
    for (int s = 0; s < 2; s++) {
        int r = (tid >> 3) + s * 32;
        int c = (tid & 7) * 4;
        float4 v = make_float4(0.f, 0.f, 0.f, 0.f);
        if (r0 + r < EE)
            v = *(const float4*)&eattr[(size_t)(r0 + r) * ED + c];
        As2[c + 0][r] = dup2(v.x);
        As2[c + 1][r] = dup2(v.y);
        As2[c + 2][r] = dup2(v.z);
        As2[c + 3][r] = dup2(v.w);
    }
#pragma unroll
    for (int s = 0; s < 2; s++) {
        int r = (tid >> 4) + s * 16;
        int c = (tid & 15) * 4;
        *(float4*)&Bs[r][c] = *(const float4*)&We[(size_t)r * C + c0 + c];
    }
    if (tid < 64) {
        int e = r0 + tid;
        ssrc[tid] = (e < EE) ? esrc[e] : 0;
        sdst[tid] = (e < EE) ? edst[e] : 0;
        satt[tid] = att[c0 + tid];
    }
    __syncthreads();

    unsigned long long acc2[4][2];
#pragma unroll
    for (int i = 0; i < 4; i++) { acc2[i][0] = 0ull; acc2[i][1] = 0ull; }
#pragma unroll
    for (int k = 0; k < 32; k++) {
        unsigned long long a2[4];
#pragma unroll
        for (int i = 0; i < 4; i++) a2[i] = As2[k][ty * 4 + i];
        ulonglong2 bb = *(const ulonglong2*)&Bs[k][tx * 4];
#pragma unroll
        for (int i = 0; i < 4; i++) {
            acc2[i][0] = ffma2(a2[i], bb.x, acc2[i][0]);
            acc2[i][1] = ffma2(a2[i], bb.y, acc2[i][1]);
        }
    }

    float4 at4 = *(const float4*)&satt[tx * 4];
#pragma unroll
    for (int i = 0; i < 4; i++) {
        int r = ty * 4 + i;
        const float4 xl4 = *(const float4*)&xl[(size_t)ssrc[r] * C + c0 + tx * 4];
        const float4 xr4 = *(const float4*)&xr[(size_t)sdst[r] * C + c0 + tx * 4];
        float2 p01 = unpk(acc2[i][0]);
        float2 p23 = unpk(acc2[i][1]);
        float v0 = p01.x + xl4.x + xr4.x; v0 = v0 > 0.f ? v0 : 0.2f * v0;
        float v1 = p01.y + xl4.y + xr4.y; v1 = v1 > 0.f ? v1 : 0.2f * v1;
        float v2 = p23.x + xl4.z + xr4.z; v2 = v2 > 0.f ? v2 : 0.2f * v2;
        float v3 = p23.y + xl4.w + xr4.w; v3 = v3 > 0.f ? v3 : 0.2f * v3;
        float p = at4.x * v0 + at4.y * v1 + at4.z * v2 + at4.w * v3;
        p += __shfl_xor_sync(0xffffffffu, p, 1);
        p += __shfl_xor_sync(0xffffffffu, p, 2);
        p += __shfl_xor_sync(0xffffffffu, p, 4);
        p += __shfl_xor_sync(0xffffffffu, p, 8);
        if (tx == 0 && r0 + r < EE) atomicAdd(&g_escore[r0 + r], p);
    }
}

// ---------------- self-loop score per node ----------------
template <int C>
__global__ void k_eself(const float* __restrict__ We, const float* __restrict__ att,
                        const float* __restrict__ xl, const float* __restrict__ xr) {
    int gw = (blockIdx.x * blockDim.x + threadIdx.x) >> 5;
    int lane = threadIdx.x & 31;
    if (gw >= NN) return;
    float la = g_loopattr[(size_t)gw * ED + lane];
    float acc = 0.f;
#pragma unroll
    for (int jj = 0; jj < C / 32; jj++) {
        int j = jj * 32 + lane;
        float v = xl[(size_t)gw * C + j] + xr[(size_t)gw * C + j];
#pragma unroll
        for (int k = 0; k < ED; k++)
            v += __shfl_sync(0xffffffffu, la, k) * We[k * C + j];
        v = v > 0.f ? v : 0.2f * v;
        acc += att[j] * v;
    }
#pragma unroll
    for (int off = 16; off; off >>= 1) acc += __shfl_xor_sync(0xffffffffu, acc, off);
    if (lane == 0) g_eself[gw] = acc;
}

// ---------------- softmax + aggregation per dst node (warp/node) ----------
template <int C>
__global__ void k_aggregate(const int* __restrict__ esrc,
                            const float* __restrict__ xl,
                            const float* __restrict__ bias,
                            float* __restrict__ outp) {
    int gw = (blockIdx.x * blockDim.x + threadIdx.x) >> 5;
    int lane = threadIdx.x & 31;
    if (gw >= NN) return;
    int beg = g_ptr[gw], end = g_ptr[gw + 1];

    float m = g_eself[gw];
    for (int t = beg + lane; t < end; t += 32) m = fmaxf(m, g_escore[g_eid[t]]);
#pragma unroll
    for (int off = 16; off; off >>= 1) m = fmaxf(m, __shfl_xor_sync(0xffffffffu, m, off));

    float4 acc[C / 128];
#pragma unroll
    for (int jj = 0; jj < C / 128; jj++) acc[jj] = make_float4(0.f, 0.f, 0.f, 0.f);
    float denom = 0.f;

    for (int t = beg; t < end; t++) {
        int eid = g_eid[t];
        float w = expf(g_escore[eid] - m);
        int s = esrc[eid];
        denom += w;
#pragma unroll
        for (int jj = 0; jj < C / 128; jj++) {
            float4 x4 = *(const float4*)&xl[(size_t)s * C + jj * 128 + lane * 4];
            acc[jj].x += w * x4.x; acc[jj].y += w * x4.y;
            acc[jj].z += w * x4.z; acc[jj].w += w * x4.w;
        }
    }
    float ws = expf(g_eself[gw] - m);
    denom += ws;
#pragma unroll
    for (int jj = 0; jj < C / 128; jj++) {
        float4 x4 = *(const float4*)&xl[(size_t)gw * C + jj * 128 + lane * 4];
        acc[jj].x += ws * x4.x; acc[jj].y += ws * x4.y;
        acc[jj].z += ws * x4.z; acc[jj].w += ws * x4.w;
    }

    float inv = 1.f / denom;
#pragma unroll
    for (int jj = 0; jj < C / 128; jj++) {
        int c = jj * 128 + lane * 4;
        float4 b4 = *(const float4*)&bias[c];
        float4 o;
        o.x = fmaxf(acc[jj].x * inv + b4.x, 0.f);
        o.y = fmaxf(acc[jj].y * inv + b4.y, 0.f);
        o.z = fmaxf(acc[jj].z * inv + b4.z, 0.f);
        o.w = fmaxf(acc[jj].w * inv + b4.w, 0.f);
        *(float4*)&outp[(size_t)gw * C + c] = o;
    }
}

// ---------------- global mean pool (smem-staged, few atomics) -------------
#define NPB 196   // nodes per block; 256 blocks * 196 >= NN
__global__ void k_pool2(const int* __restrict__ batch) {
    int tid = threadIdx.x;                 // 128 threads = H2 columns
    int n0 = blockIdx.x * NPB;
    int n1 = min(n0 + NPB, NN);
    if (n0 >= n1) return;
    int curg = batch[n0];
    float acc = 0.f;
    for (int n = n0; n < n1; n++) {
        int g = batch[n];
        if (g != curg) {
            atomicAdd(&g_pool[curg * H2 + tid], acc);
            acc = 0.f;
            curg = g;
        }
        acc += g_h2[(size_t)n * H2 + tid];
    }
    atomicAdd(&g_pool[curg * H2 + tid], acc);
}

// ---------------- MLP head (single block; cnt via binary search) ----------
__device__ __forceinline__ int lowerb(const int* b, int val) {
    int lo = 0, hi = NN;
    while (lo < hi) { int m = (lo + hi) >> 1; if (b[m] < val) lo = m + 1; else hi = m; }
    return lo;
}

__global__ void k_head(const int* __restrict__ batch,
                       const float* __restrict__ Wd1, const float* __restrict__ bd1,
                       const float* __restrict__ gma, const float* __restrict__ bta,
                       const float* __restrict__ mean, const float* __restrict__ var,
                       const float* __restrict__ Wd2, const float* __restrict__ bd2,
                       float* __restrict__ out) {
    __shared__ float sp[GG * H2];   // 32 KB
    __shared__ float sh[GG * HD];   // 16 KB
    __shared__ float scnt[GG];
    int tid = threadIdx.x;
    if (tid < GG)
        scnt[tid] = (float)(lowerb(batch, tid + 1) - lowerb(batch, tid));
    __syncthreads();
    for (int idx = tid; idx < GG * H2; idx += blockDim.x) {
        int g = idx / H2;
        sp[idx] = g_pool[idx] / fmaxf(scnt[g], 1.f);
    }
    __syncthreads();
    for (int idx = tid; idx < GG * HD; idx += blockDim.x) {
        int g = idx / HD, h = idx - g * HD;
        float a = bd1[h];
        for (int k = 0; k < H2; k++) a += sp[g * H2 + k] * Wd1[k * HD + h];
        a = (a - mean[h]) / sqrtf(var[h] + 1e-5f) * gma[h] + bta[h];
        a = a > 0.f ? a : 0.1f * a;
        sh[idx] = a;
    }
    __syncthreads();
    for (int idx = tid; idx < GG * OUTD; idx += blockDim.x) {
        int g = idx / OUTD, o = idx - g * OUTD;
        float a = bd2[o];
        for (int k = 0; k < HD; k++) a += sh[g * HD + k] * Wd2[k * OUTD + o];
        out[idx] = a;
    }
}

// ---------------- launcher ----------------
extern "C" void kernel_launch(void* const* d_in, const int* in_sizes, int n_in,
                              void* d_out, int out_size) {
    const float* node_attr = (const float*)d_in[0];
    const float* edge_attr = (const float*)d_in[1];
    const int*   esrc      = (const int*)d_in[2];
    const int*   edst      = (const int*)d_in[3];
    const int*   batch     = (const int*)d_in[4];
    const float *Wl1 = (const float*)d_in[5],  *bl1 = (const float*)d_in[6];
    const float *Wr1 = (const float*)d_in[7],  *br1 = (const float*)d_in[8];
    const float *We1 = (const float*)d_in[9],  *att1 = (const float*)d_in[10], *b1 = (const float*)d_in[11];
    const float *Wl2 = (const float*)d_in[12], *bl2 = (const float*)d_in[13];
    const float *Wr2 = (const float*)d_in[14], *br2 = (const float*)d_in[15];
    const float *We2 = (const float*)d_in[16], *att2 = (const float*)d_in[17], *b2 = (const float*)d_in[18];
    const float *Wd1 = (const float*)d_in[19], *bd1 = (const float*)d_in[20];
    const float *gma = (const float*)d_in[21], *bta = (const float*)d_in[22];
    const float *mean = (const float*)d_in[23], *var = (const float*)d_in[24];
    const float *Wd2 = (const float*)d_in[25], *bd2 = (const float*)d_in[26];
    float* out = (float*)d_out;

    float *p_xl, *p_xr, *p_h1, *p_h2, *p_escore, *p_pool;
    int *p_deg, *p_cur;
    cudaGetSymbolAddress((void**)&p_xl, g_xl);
    cudaGetSymbolAddress((void**)&p_xr, g_xr);
    cudaGetSymbolAddress((void**)&p_h1, g_h1);
    cudaGetSymbolAddress((void**)&p_h2, g_h2);
    cudaGetSymbolAddress((void**)&p_escore, g_escore);
    cudaGetSymbolAddress((void**)&p_pool, g_pool);
    cudaGetSymbolAddress((void**)&p_deg, g_deg);
    cudaGetSymbolAddress((void**)&p_cur, g_cur);

    // zero init
    cudaMemsetAsync(p_deg, 0, NN * sizeof(int), 0);
    cudaMemsetAsync(p_cur, 0, NN * sizeof(int), 0);
    cudaMemsetAsync(p_pool, 0, GG * H2 * sizeof(float), 0);

    // graph structure (shared by both layers)
    k_hist<<<(EE + 255) / 256, 256>>>(edst);
    k_scan_partial<<<NCHUNK, 1024>>>();
    k_scan_bsum<<<1, 64>>>();
    k_scan_final<<<NCHUNK, 1024>>>();
    k_scatter<<<(EE + 255) / 256, 256>>>(edst);

    int nodeWB = (NN * 32 + 255) / 256;   // warp-per-node blocks
    k_loopmean<<<nodeWB, 256>>>(edge_attr);

    // ---------------- layer 1 (DIN=128 -> H1=256) ----------------
    {
        dim3 gx((NN + 127) / 128, H1 / 128);
        k_sgemm2<<<gx, 256>>>(node_attr, Wl1, bl1, p_xl, NN, H1, DIN);
        k_sgemm2<<<gx, 256>>>(node_attr, Wr1, br1, p_xr, NN, H1, DIN);
        cudaMemsetAsync(p_escore, 0, EE * sizeof(float), 0);
        dim3 gs((EE + 63) / 64, H1 / 64);
        k_score_gemm<H1><<<gs, 256>>>(edge_attr, We1, esrc, edst, att1, p_xl, p_xr);
        k_eself<H1><<<nodeWB, 256>>>(We1, att1, p_xl, p_xr);
        k_aggregate<H1><<<nodeWB, 256>>>(esrc, p_xl, b1, p_h1);
    }
    // ---------------- layer 2 (H1=256 -> H2=128) ----------------
    {
        dim3 gx((NN + 127) / 128, H2 / 128);
        k_sgemm2<<<gx, 256>>>(p_h1, Wl2, bl2, p_xl, NN, H2, H1);
        k_sgemm2<<<gx, 256>>>(p_h1, Wr2, br2, p_xr, NN, H2, H1);
        cudaMemsetAsync(p_escore, 0, EE * sizeof(float), 0);
        dim3 gs((EE + 63) / 64, H2 / 64);
        k_score_gemm<H2><<<gs, 256>>>(edge_attr, We2, esrc, edst, att2, p_xl, p_xr);
        k_eself<H2><<<nodeWB, 256>>>(We2, att2, p_xl, p_xr);
        k_aggregate<H2><<<nodeWB, 256>>>(esrc, p_xl, b2, p_h2);
    }
    // ---------------- pool + head ----------------
    k_pool2<<<(NN + NPB - 1) / NPB, 128>>>(batch);
    k_head<<<1, 512>>>(batch, Wd1, bd1, gma, bta, mean, var, Wd2, bd2, out);
}

// round 4
// speedup vs baseline: 1.6846x; 1.5410x over previous
#include <cuda_runtime.h>
#include <cuda_bf16.h>
#include <math.h>
#include <stdint.h>

#define NN   50000
#define EE   500000
#define GG   64
#define DIN  128
#define ED   32
#define H1   256
#define H2   128
#define HD   64
#define OUTD 8
#define NCHUNK 49   // ceil(NN/1024)

// ---------------- scratch (device globals; no allocation allowed) ----------
__device__ float g_xl[(size_t)NN * H1];
__device__ float g_xr[(size_t)NN * H1];
__device__ float g_h1[(size_t)NN * H1];
__device__ float g_h2[(size_t)NN * H2];
__device__ float g_escore[EE];
__device__ float g_eself[NN];
__device__ float g_loopattr[(size_t)NN * ED];
__device__ int   g_deg[NN];
__device__ int   g_ptr[NN + 1];
__device__ int   g_cur[NN];
__device__ int   g_eid[EE];
__device__ int   g_bsum[64];
__device__ float g_pool[GG * H2];

// ======================= helpers ==========================================
__device__ __forceinline__ uint32_t smem_u32(const void* p) {
    uint32_t a;
    asm("{ .reg .u64 t; cvta.to.shared.u64 t, %1; cvt.u32.u64 %0, t; }" : "=r"(a) : "l"(p));
    return a;
}
// pack two f32 (k-order: lo_k first) into bf16x2 word (low half = lo_k)
__device__ __forceinline__ uint32_t packbf(float lo_k, float hi_k) {
    uint32_t r;
    asm("cvt.rn.bf16x2.f32 %0, %1, %2;" : "=r"(r) : "f"(hi_k), "f"(lo_k));
    return r;
}
__device__ __forceinline__ void ldm_x4(uint32_t (&r)[4], uint32_t addr) {
    asm volatile("ldmatrix.sync.aligned.m8n8.x4.shared.b16 {%0,%1,%2,%3}, [%4];"
        : "=r"(r[0]), "=r"(r[1]), "=r"(r[2]), "=r"(r[3]) : "r"(addr));
}
__device__ __forceinline__ void ldm_x2t(uint32_t (&r)[2], uint32_t addr) {
    asm volatile("ldmatrix.sync.aligned.m8n8.x2.trans.shared.b16 {%0,%1}, [%2];"
        : "=r"(r[0]), "=r"(r[1]) : "r"(addr));
}
__device__ __forceinline__ void mma_bf16(float (&c)[4], const uint32_t (&a)[4],
                                         const uint32_t (&b)[2]) {
    asm volatile("mma.sync.aligned.m16n8k16.row.col.f32.bf16.bf16.f32 "
        "{%0,%1,%2,%3},{%4,%5,%6,%7},{%8,%9},{%0,%1,%2,%3};"
        : "+f"(c[0]), "+f"(c[1]), "+f"(c[2]), "+f"(c[3])
        : "r"(a[0]), "r"(a[1]), "r"(a[2]), "r"(a[3]), "r"(b[0]), "r"(b[1]));
}

// ---------------- f32x2 packed helpers ----------------
__device__ __forceinline__ unsigned long long ffma2(unsigned long long a,
                                                    unsigned long long b,
                                                    unsigned long long c) {
    unsigned long long d;
    asm("fma.rn.f32x2 %0, %1, %2, %3;" : "=l"(d) : "l"(a), "l"(b), "l"(c));
    return d;
}
__device__ __forceinline__ unsigned long long dupf(float x) {
    unsigned long long r;
    asm("mov.b64 %0, {%1, %1};" : "=l"(r) : "f"(x));
    return r;
}
__device__ __forceinline__ float2 unpk(unsigned long long v) {
    float2 r;
    asm("mov.b64 {%0, %1}, %2;" : "=f"(r.x), "=f"(r.y) : "l"(v));
    return r;
}

// ======================= setup kernels ====================================
__global__ void k_hist(const int* __restrict__ edst) {
    int e = blockIdx.x * blockDim.x + threadIdx.x;
    if (e < EE) atomicAdd(&g_deg[edst[e]], 1);
}

__global__ void k_scan_partial() {
    __shared__ int sh[32];
    int tid = threadIdx.x;
    int i = blockIdx.x * 1024 + tid;
    int v = (i < NN) ? g_deg[i] : 0;
#pragma unroll
    for (int o = 16; o; o >>= 1) v += __shfl_xor_sync(0xffffffffu, v, o);
    if ((tid & 31) == 0) sh[tid >> 5] = v;
    __syncthreads();
    if (tid < 32) {
        int t = sh[tid];
#pragma unroll
        for (int o = 16; o; o >>= 1) t += __shfl_xor_sync(0xffffffffu, t, o);
        if (tid == 0) g_bsum[blockIdx.x] = t;
    }
}

__global__ void k_scan_bsum() {
    __shared__ int sh[64];
    int tid = threadIdx.x;
    int v = (tid < NCHUNK) ? g_bsum[tid] : 0;
    sh[tid] = v;
    __syncthreads();
    for (int off = 1; off < 64; off <<= 1) {
        int t = (tid >= off) ? sh[tid - off] : 0;
        __syncthreads();
        sh[tid] += t;
        __syncthreads();
    }
    if (tid < NCHUNK) g_bsum[tid] = sh[tid] - v;   // exclusive
    if (tid == 0) g_ptr[NN] = EE;
}

__global__ void k_scan_final() {
    __shared__ int sh[32];
    int tid = threadIdx.x, lane = tid & 31, wid = tid >> 5;
    int i = blockIdx.x * 1024 + tid;
    int v = (i < NN) ? g_deg[i] : 0;
    int incl = v;
#pragma unroll
    for (int o = 1; o < 32; o <<= 1) {
        int t = __shfl_up_sync(0xffffffffu, incl, o);
        if (lane >= o) incl += t;
    }
    if (lane == 31) sh[wid] = incl;
    __syncthreads();
    if (wid == 0) {
        int t = sh[lane];
#pragma unroll
        for (int o = 1; o < 32; o <<= 1) {
            int u = __shfl_up_sync(0xffffffffu, t, o);
            if (lane >= o) t += u;
        }
        sh[lane] = t;
    }
    __syncthreads();
    int base = g_bsum[blockIdx.x] + (wid ? sh[wid - 1] : 0);
    if (i < NN) g_ptr[i] = base + incl - v;
}

__global__ void k_scatter(const int* __restrict__ edst) {
    int e = blockIdx.x * blockDim.x + threadIdx.x;
    if (e >= EE) return;
    int d = edst[e];
    int pos = atomicAdd(&g_cur[d], 1);
    g_eid[g_ptr[d] + pos] = e;
}

__global__ void k_loopmean(const float* __restrict__ eattr) {
    int gw = (blockIdx.x * blockDim.x + threadIdx.x) >> 5;
    int lane = threadIdx.x & 31;
    if (gw >= NN) return;
    int beg = g_ptr[gw], end = g_ptr[gw + 1];
    float acc = 0.f;
    for (int t = beg; t < end; t++)
        acc += eattr[(size_t)g_eid[t] * ED + lane];
    g_loopattr[(size_t)gw * ED + lane] = acc / fmaxf((float)(end - beg), 1.f);
}

// ======================= mma.sync bf16x3 node GEMM ========================
// C[M,Nc] = A[M,KTOT] @ W[KTOT,Nc] + bias, fp32 in/out.
// grid (ceil(M/128), Nc/64, 2); z selects (W0,b0,out0)/(W1,b1,out1).
// CTA tile 128x64, K-chunk 32, 8 warps as 4(M) x 2(N), warp tile 32x32.
#define STRA 20   // A smem row stride in uint32 (40 bf16)
#define STRB 36   // B smem row stride in uint32 (72 bf16)

template <int KTOT>
__global__ void __launch_bounds__(256, 2)
k_mma_node(const float* __restrict__ A,
           const float* __restrict__ W0, const float* __restrict__ bias0, float* __restrict__ out0,
           const float* __restrict__ W1, const float* __restrict__ bias1, float* __restrict__ out1,
           int M, int Nc) {
    __shared__ __align__(16) uint32_t sAhi[128 * STRA];
    __shared__ __align__(16) uint32_t sAlo[128 * STRA];
    __shared__ __align__(16) uint32_t sBhi[32 * STRB];
    __shared__ __align__(16) uint32_t sBlo[32 * STRB];

    int tid = threadIdx.x, lane = tid & 31, w = tid >> 5;
    int wm = w & 3, wn = w >> 2;
    const float* W    = blockIdx.z ? W1 : W0;
    const float* bias = blockIdx.z ? bias1 : bias0;
    float* out        = blockIdx.z ? out1 : out0;
    int row0 = blockIdx.x * 128, c0 = blockIdx.y * 64;

    uint32_t aHiB = smem_u32(sAhi), aLoB = smem_u32(sAlo);
    uint32_t bHiB = smem_u32(sBhi), bLoB = smem_u32(sBlo);

    float acc[2][4][4];
#pragma unroll
    for (int i = 0; i < 2; i++)
#pragma unroll
        for (int j = 0; j < 4; j++)
#pragma unroll
            for (int q = 0; q < 4; q++) acc[i][j][q] = 0.f;

    for (int k0 = 0; k0 < KTOT; k0 += 32) {
        // ---- A chunk 128x32 f32 -> hi/lo bf16 smem
#pragma unroll
        for (int t = 0; t < 4; t++) {
            int idx = tid + t * 256;
            int r = idx >> 3, c4 = (idx & 7) * 4;
            float4 v = make_float4(0.f, 0.f, 0.f, 0.f);
            if (row0 + r < M)
                v = *(const float4*)&A[(size_t)(row0 + r) * KTOT + k0 + c4];
            uint32_t h01 = packbf(v.x, v.y);
            uint32_t h23 = packbf(v.z, v.w);
            float r0 = v.x - __uint_as_float(h01 << 16);
            float r1 = v.y - __uint_as_float(h01 & 0xffff0000u);
            float r2 = v.z - __uint_as_float(h23 << 16);
            float r3 = v.w - __uint_as_float(h23 & 0xffff0000u);
            int o = r * STRA + (c4 >> 1);
            sAhi[o] = h01; sAhi[o + 1] = h23;
            sAlo[o] = packbf(r0, r1); sAlo[o + 1] = packbf(r2, r3);
        }
        // ---- B chunk 32x64 f32 -> hi/lo bf16 smem
#pragma unroll
        for (int t = 0; t < 2; t++) {
            int idx = tid + t * 256;
            int r = idx >> 4, c4 = (idx & 15) * 4;
            float4 v = *(const float4*)&W[(size_t)(k0 + r) * Nc + c0 + c4];
            uint32_t h01 = packbf(v.x, v.y);
            uint32_t h23 = packbf(v.z, v.w);
            float r0 = v.x - __uint_as_float(h01 << 16);
            float r1 = v.y - __uint_as_float(h01 & 0xffff0000u);
            float r2 = v.z - __uint_as_float(h23 << 16);
            float r3 = v.w - __uint_as_float(h23 & 0xffff0000u);
            int o = r * STRB + (c4 >> 1);
            sBhi[o] = h01; sBhi[o + 1] = h23;
            sBlo[o] = packbf(r0, r1); sBlo[o + 1] = packbf(r2, r3);
        }
        __syncthreads();

#pragma unroll
        for (int s = 0; s < 2; s++) {
            uint32_t aH[2][4], aL[2][4];
#pragma unroll
            for (int i = 0; i < 2; i++) {
                int tile = lane >> 3, rr = lane & 7;
                int row = wm * 32 + i * 16 + (tile & 1) * 8 + rr;
                int kk = s * 16 + (tile >> 1) * 8;
                uint32_t off = (uint32_t)(row * STRA) * 4u + (uint32_t)kk * 2u;
                ldm_x4(aH[i], aHiB + off);
                ldm_x4(aL[i], aLoB + off);
            }
            uint32_t bH[4][2], bL[4][2];
#pragma unroll
            for (int j = 0; j < 4; j++) {
                int krow = s * 16 + (lane & 15);
                int ncol = wn * 32 + j * 8;
                uint32_t off = (uint32_t)(krow * STRB) * 4u + (uint32_t)ncol * 2u;
                ldm_x2t(bH[j], bHiB + off);
                ldm_x2t(bL[j], bLoB + off);
            }
#pragma unroll
            for (int i = 0; i < 2; i++)
#pragma unroll
                for (int j = 0; j < 4; j++) {
                    mma_bf16(acc[i][j], aH[i], bH[j]);
                    mma_bf16(acc[i][j], aH[i], bL[j]);
                    mma_bf16(acc[i][j], aL[i], bH[j]);
                }
        }
        __syncthreads();
    }

    // ---- epilogue
    int g = lane >> 2, tg = lane & 3;
#pragma unroll
    for (int i = 0; i < 2; i++) {
        int r1 = row0 + wm * 32 + i * 16 + g;
        int r2 = r1 + 8;
#pragma unroll
        for (int j = 0; j < 4; j++) {
            int col = c0 + wn * 32 + j * 8 + tg * 2;
            float2 bv = *(const float2*)&bias[col];
            if (r1 < M) {
                float2 o = make_float2(acc[i][j][0] + bv.x, acc[i][j][1] + bv.y);
                *(float2*)&out[(size_t)r1 * Nc + col] = o;
            }
            if (r2 < M) {
                float2 o = make_float2(acc[i][j][2] + bv.x, acc[i][j][3] + bv.y);
                *(float2*)&out[(size_t)r2 * Nc + col] = o;
            }
        }
    }
}

// ======================= fused edge-score GEMM (no atomics) ===============
// 64 edges x ALL C cols per block. score_e = sum_c att[c]*leaky(ew+xl[s]+xr[d]).
// f32x2 packs edge PAIRS; each warp owns 8 edges, full reduction in-warp.
template <int C>
__global__ void __launch_bounds__(256)
k_score2(const float* __restrict__ eattr, const float* __restrict__ We,
         const int* __restrict__ esrc, const int* __restrict__ edst,
         const float* __restrict__ att,
         const float* __restrict__ xl, const float* __restrict__ xr) {
    constexpr int CPL = C / 32;               // cols per lane
    __shared__ uint32_t AsU[ED][64];          // [k][edge] fp32 bits, 8KB
    __shared__ float Bs[ED][C];               // We [k][col]
    __shared__ int ssrc[64], sdst[64];
    int tid = threadIdx.x, w = tid >> 5, lane = tid & 31;
    int r0 = blockIdx.x * 64;

    for (int idx = tid; idx < 64 * 8; idx += 256) {
        int e = idx >> 3, c4 = (idx & 7) * 4;
        float4 v = make_float4(0.f, 0.f, 0.f, 0.f);
        if (r0 + e < EE) v = *(const float4*)&eattr[(size_t)(r0 + e) * ED + c4];
        AsU[c4 + 0][e] = __float_as_uint(v.x);
        AsU[c4 + 1][e] = __float_as_uint(v.y);
        AsU[c4 + 2][e] = __float_as_uint(v.z);
        AsU[c4 + 3][e] = __float_as_uint(v.w);
    }
    for (int idx = tid; idx < ED * (C / 4); idx += 256) {
        int k = idx / (C / 4), c = (idx % (C / 4)) * 4;
        *(float4*)&Bs[k][c] = *(const float4*)&We[(size_t)k * C + c];
    }
    if (tid < 64) {
        int e = r0 + tid;
        ssrc[tid] = (e < EE) ? esrc[e] : 0;
        sdst[tid] = (e < EE) ? edst[e] : 0;
    }
    __syncthreads();

    int cb = lane * CPL;
    unsigned long long acc2[4][CPL];
#pragma unroll
    for (int p = 0; p < 4; p++)
#pragma unroll
        for (int j = 0; j < CPL; j++) acc2[p][j] = 0ull;

#pragma unroll
    for (int k = 0; k < ED; k++) {
        ulonglong2 aA = *(const ulonglong2*)&AsU[k][w * 8];
        ulonglong2 aB = *(const ulonglong2*)&AsU[k][w * 8 + 4];
        unsigned long long a[4] = {aA.x, aA.y, aB.x, aB.y};
#pragma unroll
        for (int j = 0; j < CPL; j++) {
            unsigned long long b = dupf(Bs[k][cb + j]);
#pragma unroll
            for (int p = 0; p < 4; p++)
                acc2[p][j] = ffma2(a[p], b, acc2[p][j]);
        }
    }

    float attv[CPL];
#pragma unroll
    for (int j = 0; j < CPL; j += 4)
        *(float4*)&attv[j] = *(const float4*)&att[cb + j];

#pragma unroll
    for (int p = 0; p < 4; p++) {
        int e0i = w * 8 + 2 * p, e1i = e0i + 1;
        const float* xl0 = &xl[(size_t)ssrc[e0i] * C + cb];
        const float* xr0 = &xr[(size_t)sdst[e0i] * C + cb];
        const float* xl1 = &xl[(size_t)ssrc[e1i] * C + cb];
        const float* xr1 = &xr[(size_t)sdst[e1i] * C + cb];
        float a0[CPL], b0[CPL], a1[CPL], b1[CPL];
#pragma unroll
        for (int j = 0; j < CPL; j += 4) {
            *(float4*)&a0[j] = *(const float4*)&xl0[j];
            *(float4*)&b0[j] = *(const float4*)&xr0[j];
            *(float4*)&a1[j] = *(const float4*)&xl1[j];
            *(float4*)&b1[j] = *(const float4*)&xr1[j];
        }
        float pe0 = 0.f, pe1 = 0.f;
#pragma unroll
        for (int j = 0; j < CPL; j++) {
            float2 v = unpk(acc2[p][j]);
            float t0 = v.x + a0[j] + b0[j]; t0 = t0 > 0.f ? t0 : 0.2f * t0;
            float t1 = v.y + a1[j] + b1[j]; t1 = t1 > 0.f ? t1 : 0.2f * t1;
            pe0 += attv[j] * t0;
            pe1 += attv[j] * t1;
        }
#pragma unroll
        for (int o = 16; o; o >>= 1) {
            pe0 += __shfl_xor_sync(0xffffffffu, pe0, o);
            pe1 += __shfl_xor_sync(0xffffffffu, pe1, o);
        }
        if (lane == 0) {
            if (r0 + e0i < EE) g_escore[r0 + e0i] = pe0;
            if (r0 + e1i < EE) g_escore[r0 + e1i] = pe1;
        }
    }
}

// ======================= self-loop score per node =========================
template <int C>
__global__ void k_eself(const float* __restrict__ We, const float* __restrict__ att,
                        const float* __restrict__ xl, const float* __restrict__ xr) {
    int gw = (blockIdx.x * blockDim.x + threadIdx.x) >> 5;
    int lane = threadIdx.x & 31;
    if (gw >= NN) return;
    float la = g_loopattr[(size_t)gw * ED + lane];
    float acc = 0.f;
#pragma unroll
    for (int jj = 0; jj < C / 32; jj++) {
        int j = jj * 32 + lane;
        float v = xl[(size_t)gw * C + j] + xr[(size_t)gw * C + j];
#pragma unroll
        for (int k = 0; k < ED; k++)
            v += __shfl_sync(0xffffffffu, la, k) * We[k * C + j];
        v = v > 0.f ? v : 0.2f * v;
        acc += att[j] * v;
    }
#pragma unroll
    for (int off = 16; off; off >>= 1) acc += __shfl_xor_sync(0xffffffffu, acc, off);
    if (lane == 0) g_eself[gw] = acc;
}

// ======================= softmax + aggregation (warp/node) ================
template <int C>
__global__ void k_aggregate(const int* __restrict__ esrc,
                            const float* __restrict__ xl,
                            const float* __restrict__ bias,
                            float* __restrict__ outp) {
    int gw = (blockIdx.x * blockDim.x + threadIdx.x) >> 5;
    int lane = threadIdx.x & 31;
    if (gw >= NN) return;
    int beg = g_ptr[gw], end = g_ptr[gw + 1];

    float m = g_eself[gw];
    for (int t = beg + lane; t < end; t += 32) m = fmaxf(m, g_escore[g_eid[t]]);
#pragma unroll
    for (int off = 16; off; off >>= 1) m = fmaxf(m, __shfl_xor_sync(0xffffffffu, m, off));

    float4 acc[C / 128];
#pragma unroll
    for (int jj = 0; jj < C / 128; jj++) acc[jj] = make_float4(0.f, 0.f, 0.f, 0.f);
    float denom = 0.f;

    for (int t = beg; t < end; t++) {
        int eid = g_eid[t];
        float w = expf(g_escore[eid] - m);
        int s = esrc[eid];
        denom += w;
#pragma unroll
        for (int jj = 0; jj < C / 128; jj++) {
            float4 x4 = *(const float4*)&xl[(size_t)s * C + jj * 128 + lane * 4];
            acc[jj].x += w * x4.x; acc[jj].y += w * x4.y;
            acc[jj].z += w * x4.z; acc[jj].w += w * x4.w;
        }
    }
    float ws = expf(g_eself[gw] - m);
    denom += ws;
#pragma unroll
    for (int jj = 0; jj < C / 128; jj++) {
        float4 x4 = *(const float4*)&xl[(size_t)gw * C + jj * 128 + lane * 4];
        acc[jj].x += ws * x4.x; acc[jj].y += ws * x4.y;
        acc[jj].z += ws * x4.z; acc[jj].w += ws * x4.w;
    }

    float inv = 1.f / denom;
#pragma unroll
    for (int jj = 0; jj < C / 128; jj++) {
        int c = jj * 128 + lane * 4;
        float4 b4 = *(const float4*)&bias[c];
        float4 o;
        o.x = fmaxf(acc[jj].x * inv + b4.x, 0.f);
        o.y = fmaxf(acc[jj].y * inv + b4.y, 0.f);
        o.z = fmaxf(acc[jj].z * inv + b4.z, 0.f);
        o.w = fmaxf(acc[jj].w * inv + b4.w, 0.f);
        *(float4*)&outp[(size_t)gw * C + c] = o;
    }
}

// ======================= global mean pool =================================
#define NPB 196
__global__ void k_pool2(const int* __restrict__ batch) {
    int tid = threadIdx.x;                 // 128 threads = H2 columns
    int n0 = blockIdx.x * NPB;
    int n1 = min(n0 + NPB, NN);
    if (n0 >= n1) return;
    int curg = batch[n0];
    float acc = 0.f;
    for (int n = n0; n < n1; n++) {
        int g = batch[n];
        if (g != curg) {
            atomicAdd(&g_pool[curg * H2 + tid], acc);
            acc = 0.f;
            curg = g;
        }
        acc += g_h2[(size_t)n * H2 + tid];
    }
    atomicAdd(&g_pool[curg * H2 + tid], acc);
}

// ======================= MLP head =========================================
__device__ __forceinline__ int lowerb(const int* b, int val) {
    int lo = 0, hi = NN;
    while (lo < hi) { int m = (lo + hi) >> 1; if (b[m] < val) lo = m + 1; else hi = m; }
    return lo;
}

__global__ void k_head(const int* __restrict__ batch,
                       const float* __restrict__ Wd1, const float* __restrict__ bd1,
                       const float* __restrict__ gma, const float* __restrict__ bta,
                       const float* __restrict__ mean, const float* __restrict__ var,
                       const float* __restrict__ Wd2, const float* __restrict__ bd2,
                       float* __restrict__ out) {
    __shared__ float sp[GG * H2];
    __shared__ float sh[GG * HD];
    __shared__ float scnt[GG];
    int tid = threadIdx.x;
    if (tid < GG)
        scnt[tid] = (float)(lowerb(batch, tid + 1) - lowerb(batch, tid));
    __syncthreads();
    for (int idx = tid; idx < GG * H2; idx += blockDim.x) {
        int g = idx / H2;
        sp[idx] = g_pool[idx] / fmaxf(scnt[g], 1.f);
    }
    __syncthreads();
    for (int idx = tid; idx < GG * HD; idx += blockDim.x) {
        int g = idx / HD, h = idx - g * HD;
        float a = bd1[h];
        for (int k = 0; k < H2; k++) a += sp[g * H2 + k] * Wd1[k * HD + h];
        a = (a - mean[h]) / sqrtf(var[h] + 1e-5f) * gma[h] + bta[h];
        a = a > 0.f ? a : 0.1f * a;
        sh[idx] = a;
    }
    __syncthreads();
    for (int idx = tid; idx < GG * OUTD; idx += blockDim.x) {
        int g = idx / OUTD, o = idx - g * OUTD;
        float a = bd2[o];
        for (int k = 0; k < HD; k++) a += sh[g * HD + k] * Wd2[k * OUTD + o];
        out[idx] = a;
    }
}

// ======================= launcher =========================================
extern "C" void kernel_launch(void* const* d_in, const int* in_sizes, int n_in,
                              void* d_out, int out_size) {
    const float* node_attr = (const float*)d_in[0];
    const float* edge_attr = (const float*)d_in[1];
    const int*   esrc      = (const int*)d_in[2];
    const int*   edst      = (const int*)d_in[3];
    const int*   batch     = (const int*)d_in[4];
    const float *Wl1 = (const float*)d_in[5],  *bl1 = (const float*)d_in[6];
    const float *Wr1 = (const float*)d_in[7],  *br1 = (const float*)d_in[8];
    const float *We1 = (const float*)d_in[9],  *att1 = (const float*)d_in[10], *b1 = (const float*)d_in[11];
    const float *Wl2 = (const float*)d_in[12], *bl2 = (const float*)d_in[13];
    const float *Wr2 = (const float*)d_in[14], *br2 = (const float*)d_in[15];
    const float *We2 = (const float*)d_in[16], *att2 = (const float*)d_in[17], *b2 = (const float*)d_in[18];
    const float *Wd1 = (const float*)d_in[19], *bd1 = (const float*)d_in[20];
    const float *gma = (const float*)d_in[21], *bta = (const float*)d_in[22];
    const float *mean = (const float*)d_in[23], *var = (const float*)d_in[24];
    const float *Wd2 = (const float*)d_in[25], *bd2 = (const float*)d_in[26];
    float* out = (float*)d_out;

    float *p_xl, *p_xr, *p_h1, *p_h2, *p_pool;
    int *p_deg, *p_cur;
    cudaGetSymbolAddress((void**)&p_xl, g_xl);
    cudaGetSymbolAddress((void**)&p_xr, g_xr);
    cudaGetSymbolAddress((void**)&p_h1, g_h1);
    cudaGetSymbolAddress((void**)&p_h2, g_h2);
    cudaGetSymbolAddress((void**)&p_pool, g_pool);
    cudaGetSymbolAddress((void**)&p_deg, g_deg);
    cudaGetSymbolAddress((void**)&p_cur, g_cur);

    cudaMemsetAsync(p_deg, 0, NN * sizeof(int), 0);
    cudaMemsetAsync(p_cur, 0, NN * sizeof(int), 0);
    cudaMemsetAsync(p_pool, 0, GG * H2 * sizeof(float), 0);

    int nodeWB = (NN * 32 + 255) / 256;   // warp-per-node blocks
    int rowT = (NN + 127) / 128;          // 391

    // setup + layer-1 node GEMM interleaved (GEMM depends only on inputs)
    k_hist<<<(EE + 255) / 256, 256>>>(edst);
    k_scan_partial<<<NCHUNK, 1024>>>();
    k_scan_bsum<<<1, 64>>>();
    k_mma_node<DIN><<<dim3(rowT, H1 / 64, 2), 256>>>(
        node_attr, Wl1, bl1, p_xl, Wr1, br1, p_xr, NN, H1);
    k_scan_final<<<NCHUNK, 1024>>>();
    k_scatter<<<(EE + 255) / 256, 256>>>(edst);
    k_loopmean<<<nodeWB, 256>>>(edge_attr);

    // ---------------- layer 1 ----------------
    k_score2<H1><<<(EE + 63) / 64, 256>>>(edge_attr, We1, esrc, edst, att1, p_xl, p_xr);
    k_eself<H1><<<nodeWB, 256>>>(We1, att1, p_xl, p_xr);
    k_aggregate<H1><<<nodeWB, 256>>>(esrc, p_xl, b1, p_h1);

    // ---------------- layer 2 ----------------
    k_mma_node<H1><<<dim3(rowT, H2 / 64, 2), 256>>>(
        p_h1, Wl2, bl2, p_xl, Wr2, br2, p_xr, NN, H2);
    k_score2<H2><<<(EE + 63) / 64, 256>>>(edge_attr, We2, esrc, edst, att2, p_xl, p_xr);
    k_eself<H2><<<nodeWB, 256>>>(We2, att2, p_xl, p_xr);
    k_aggregate<H2><<<nodeWB, 256>>>(esrc, p_xl, b2, p_h2);

    // ---------------- pool + head ----------------
    k_pool2<<<(NN + NPB - 1) / NPB, 128>>>(batch);
    k_head<<<1, 512>>>(batch, Wd1, bd1, gma, bta, mean, var, Wd2, bd2, out);
}